// round 11
// baseline (speedup 1.0000x reference)
#include <cuda_runtime.h>
#include <math.h>
#include <stdint.h>

#define C_DIM 512
#define AREA  4096
#define BATCH 4
#define GROUPS 32
#define CPG   16
#define GRP_F4 16384   // (CPG*AREA)/4 float4s per group

// ---------------- scratch (static device globals; no allocation) ----------------
// Layouts: g_xn, g_q, g_k, g_ao are [b][a][c] (c contiguous);
//          g_v is [b][c][a] (a contiguous); g_attn is [b][i][j].
__device__ float g_xn  [(size_t)BATCH * C_DIM * AREA];
__device__ float g_q   [(size_t)BATCH * C_DIM * AREA];
__device__ float g_k   [(size_t)BATCH * C_DIM * AREA];
__device__ float g_v   [(size_t)BATCH * C_DIM * AREA];
__device__ float g_ao  [(size_t)BATCH * C_DIM * AREA];
__device__ float g_attn[(size_t)BATCH * AREA * AREA];

// ---------------- GroupNorm + transpose to [a][c] ----------------
__global__ void groupnorm_t_kernel(const float* __restrict__ net,
                                   const float* __restrict__ gscale,
                                   const float* __restrict__ gbias,
                                   float* __restrict__ xnt) {
    const int bg = blockIdx.x;          // 0..127
    const int b  = bg >> 5;
    const int gi = bg & 31;
    const size_t base = ((size_t)b * C_DIM + (size_t)gi * CPG) * AREA;
    const float4* src4 = (const float4*)(net + base);
    const int tid = threadIdx.x;

    // ---- stats ----
    float s = 0.f, ss = 0.f;
    for (int i = tid; i < GRP_F4; i += 256) {
        float4 v = src4[i];
        s  += v.x + v.y + v.z + v.w;
        ss += v.x*v.x + v.y*v.y + v.z*v.z + v.w*v.w;
    }
    __shared__ float red[512];
    red[tid] = s; red[256 + tid] = ss;
    __syncthreads();
    for (int off = 128; off > 0; off >>= 1) {
        if (tid < off) {
            red[tid]       += red[tid + off];
            red[256 + tid] += red[256 + tid + off];
        }
        __syncthreads();
    }
    const float inv_n = 1.0f / 65536.0f;
    const float mu   = red[0] * inv_n;
    const float var  = red[256] * inv_n - mu * mu;
    const float rstd = rsqrtf(var + 1e-6f);

    // ---- normalize + transpose: tiles of 16c x 64a ----
    __shared__ float T[16 * 68];
    const int c_l = tid >> 4;          // load phase: channel 0..15
    const int a4  = tid & 15;          // load phase: float4 index within 64a
    const int a_l = tid >> 2;          // store phase: a 0..63
    const int cq  = tid & 3;           // store phase: c-quad 0..3
    const float sc = gscale[gi * CPG + c_l] * rstd;
    const float bi = gbias[gi * CPG + c_l];

    for (int a0 = 0; a0 < AREA; a0 += 64) {
        float4 v = src4[c_l * (AREA/4) + (a0 >> 2) + a4];
        v.x = (v.x - mu) * sc + bi;
        v.y = (v.y - mu) * sc + bi;
        v.z = (v.z - mu) * sc + bi;
        v.w = (v.w - mu) * sc + bi;
        __syncthreads();               // previous tile's reads done
        *(float4*)&T[c_l * 68 + a4 * 4] = v;
        __syncthreads();
        float4 w;
        w.x = T[(cq * 4 + 0) * 68 + a_l];
        w.y = T[(cq * 4 + 1) * 68 + a_l];
        w.z = T[(cq * 4 + 2) * 68 + a_l];
        w.w = T[(cq * 4 + 3) * 68 + a_l];
        *(float4*)&xnt[((size_t)b * AREA + a0 + a_l) * C_DIM + gi * CPG + cq * 4] = w;
    }
}

// ---------------- tf32 helpers ----------------
__device__ __forceinline__ uint32_t f2tf(float x) {
    uint32_t r;
    asm("cvt.rna.tf32.f32 %0, %1;" : "=r"(r) : "f"(x));
    return r;
}

// ---------------- unified K-contiguous tensor-core GEMM ----------------
// C[m,n] = alpha * sum_k A[m][k]*B[n][k] + biasM[m] + biasN[n] + resid[m,n]
// A row-major [M,K], B row-major [N,K] — both K-contiguous.
// Block 128x128, BK=32, 256 threads (8 warps of 64x32), mma m16n8k8 tf32.
// Smem: k-permuted layout p(k) = (k&3)*8 + (k>>2), row stride 34 words.
//   -> each fragment k-pair (kb+tg, kb+tg+4) is one aligned LDS.64, conflict-free.
// Register-staged prefetch of the next k-tile overlaps global latency with MMA.
__global__ __launch_bounds__(256, 1)
void gemm_kc(const float* __restrict__ A, const float* __restrict__ B,
             float* __restrict__ C,
             int M, int N, int K,
             size_t sAb, size_t sBb, size_t sCb,
             float alpha,
             const float* __restrict__ biasM,
             const float* __restrict__ biasN,
             const float* __restrict__ resid, size_t sRb) {
    __shared__ uint32_t As[128 * 34];
    __shared__ uint32_t Bs[128 * 34];

    const int tid  = threadIdx.x;
    const int warp = tid >> 5;
    const int lane = tid & 31;
    const int g    = lane >> 2;     // 0..7
    const int tg   = lane & 3;      // 0..3
    const int warpM = warp >> 2;    // 0..1  (64 rows)
    const int warpN = warp & 3;     // 0..3  (32 cols)
    const int n0 = blockIdx.x * 128;
    const int m0 = blockIdx.y * 128;
    const int bz = blockIdx.z;

    const float4* A4 = (const float4*)(A + (size_t)bz * sAb);
    const float4* B4 = (const float4*)(B + (size_t)bz * sBb);
    const int K4 = K >> 2;

    // fill coordinates: per j-chunk, row = (tid>>3) + j*32, k4-chunk = tid&7
    const int kk4  = tid & 7;
    const int mrow = tid >> 3;

    float acc[4][4][4];
    #pragma unroll
    for (int mt = 0; mt < 4; ++mt)
        #pragma unroll
        for (int nt = 0; nt < 4; ++nt)
            #pragma unroll
            for (int r = 0; r < 4; ++r) acc[mt][nt][r] = 0.f;

    // prefetch tile 0
    float4 rA[4], rB[4];
    #pragma unroll
    for (int j = 0; j < 4; ++j) {
        rA[j] = A4[(size_t)(m0 + mrow + j * 32) * K4 + kk4];
        rB[j] = B4[(size_t)(n0 + mrow + j * 32) * K4 + kk4];
    }

    const int T = K >> 5;
    for (int t = 0; t < T; ++t) {
        __syncthreads();   // previous MMA reads complete before overwrite
        #pragma unroll
        for (int j = 0; j < 4; ++j) {
            uint32_t* dA = &As[(mrow + j * 32) * 34 + kk4];
            dA[0]  = f2tf(rA[j].x); dA[8]  = f2tf(rA[j].y);
            dA[16] = f2tf(rA[j].z); dA[24] = f2tf(rA[j].w);
            uint32_t* dB = &Bs[(mrow + j * 32) * 34 + kk4];
            dB[0]  = f2tf(rB[j].x); dB[8]  = f2tf(rB[j].y);
            dB[16] = f2tf(rB[j].z); dB[24] = f2tf(rB[j].w);
        }
        __syncthreads();
        if (t + 1 < T) {
            const int kb4 = (t + 1) * 8;
            #pragma unroll
            for (int j = 0; j < 4; ++j) {
                rA[j] = A4[(size_t)(m0 + mrow + j * 32) * K4 + kb4 + kk4];
                rB[j] = B4[(size_t)(n0 + mrow + j * 32) * K4 + kb4 + kk4];
            }
        }
        #pragma unroll
        for (int ks = 0; ks < 4; ++ks) {
            const int pk = tg * 8 + 2 * ks;
            uint2 ax[4], ay[4], bv[4];
            #pragma unroll
            for (int mt = 0; mt < 4; ++mt) {
                const int mb = warpM * 64 + mt * 16;
                ax[mt] = *(const uint2*)&As[(mb + g) * 34 + pk];
                ay[mt] = *(const uint2*)&As[(mb + g + 8) * 34 + pk];
            }
            #pragma unroll
            for (int nt = 0; nt < 4; ++nt)
                bv[nt] = *(const uint2*)&Bs[(warpN * 32 + nt * 8 + g) * 34 + pk];
            #pragma unroll
            for (int mt = 0; mt < 4; ++mt)
                #pragma unroll
                for (int nt = 0; nt < 4; ++nt) {
                    float* c = acc[mt][nt];
                    asm volatile(
                        "mma.sync.aligned.m16n8k8.row.col.f32.tf32.tf32.f32 "
                        "{%0,%1,%2,%3}, {%4,%5,%6,%7}, {%8,%9}, {%0,%1,%2,%3};\n"
                        : "+f"(c[0]), "+f"(c[1]), "+f"(c[2]), "+f"(c[3])
                        : "r"(ax[mt].x), "r"(ay[mt].x), "r"(ax[mt].y), "r"(ay[mt].y),
                          "r"(bv[nt].x), "r"(bv[nt].y));
                }
        }
    }

    // ---- epilogue ----
    float* Cb = C + (size_t)bz * sCb;
    const float* Rb = resid ? (resid + (size_t)bz * sRb) : nullptr;

    #pragma unroll
    for (int mt = 0; mt < 4; ++mt) {
        const int mb = m0 + warpM * 64 + mt * 16;
        const int r0 = mb + g, r1 = mb + g + 8;
        const float bm0 = biasM ? biasM[r0] : 0.f;
        const float bm1 = biasM ? biasM[r1] : 0.f;
        #pragma unroll
        for (int nt = 0; nt < 4; ++nt) {
            const int nn = n0 + warpN * 32 + nt * 8 + 2 * tg;
            const float bn0 = biasN ? biasN[nn]     : 0.f;
            const float bn1 = biasN ? biasN[nn + 1] : 0.f;
            const size_t o0 = (size_t)r0 * N + nn;
            const size_t o1 = (size_t)r1 * N + nn;
            float2 v0 = { alpha * acc[mt][nt][0] + bm0 + bn0,
                          alpha * acc[mt][nt][1] + bm0 + bn1 };
            float2 v1 = { alpha * acc[mt][nt][2] + bm1 + bn0,
                          alpha * acc[mt][nt][3] + bm1 + bn1 };
            if (Rb) {
                v0.x += Rb[o0]; v0.y += Rb[o0 + 1];
                v1.x += Rb[o1]; v1.y += Rb[o1 + 1];
            }
            *(float2*)&Cb[o0] = v0;
            *(float2*)&Cb[o1] = v1;
        }
    }
}

// ---------------- softmax over rows of length 4096 ----------------
__global__ void softmax4096(float* __restrict__ attn) {
    const size_t row = blockIdx.x;
    float* p = attn + row * AREA;
    const int tid = threadIdx.x;

    float4 r[4];
    #pragma unroll
    for (int i = 0; i < 4; ++i)
        r[i] = *(const float4*)&p[(tid + i * 256) * 4];

    float m = -3.0e38f;
    #pragma unroll
    for (int i = 0; i < 4; ++i)
        m = fmaxf(m, fmaxf(fmaxf(r[i].x, r[i].y), fmaxf(r[i].z, r[i].w)));
    __shared__ float red[256];
    red[tid] = m; __syncthreads();
    for (int off = 128; off > 0; off >>= 1) {
        if (tid < off) red[tid] = fmaxf(red[tid], red[tid + off]);
        __syncthreads();
    }
    m = red[0];
    __syncthreads();

    float s = 0.f;
    #pragma unroll
    for (int i = 0; i < 4; ++i) {
        r[i].x = __expf(r[i].x - m); r[i].y = __expf(r[i].y - m);
        r[i].z = __expf(r[i].z - m); r[i].w = __expf(r[i].w - m);
        s += r[i].x + r[i].y + r[i].z + r[i].w;
    }
    red[tid] = s; __syncthreads();
    for (int off = 128; off > 0; off >>= 1) {
        if (tid < off) red[tid] += red[tid + off];
        __syncthreads();
    }
    const float inv = 1.0f / red[0];

    #pragma unroll
    for (int i = 0; i < 4; ++i) {
        r[i].x *= inv; r[i].y *= inv; r[i].z *= inv; r[i].w *= inv;
        *(float4*)&p[(tid + i * 256) * 4] = r[i];
    }
}

// ---------------- launch ----------------
extern "C" void kernel_launch(void* const* d_in, const int* in_sizes, int n_in,
                              void* d_out, int out_size) {
    const float* net = (const float*)d_in[0];
    const float* gns = (const float*)d_in[1];
    const float* gnb = (const float*)d_in[2];
    const float* wq  = (const float*)d_in[3];
    const float* bq  = (const float*)d_in[4];
    const float* wk  = (const float*)d_in[5];
    const float* bk  = (const float*)d_in[6];
    const float* wv  = (const float*)d_in[7];
    const float* bv  = (const float*)d_in[8];
    const float* wo  = (const float*)d_in[9];
    const float* bo  = (const float*)d_in[10];
    float* out = (float*)d_out;

    float *xn, *q, *k, *v, *ao, *attn;
    cudaGetSymbolAddress((void**)&xn,   g_xn);
    cudaGetSymbolAddress((void**)&q,    g_q);
    cudaGetSymbolAddress((void**)&k,    g_k);
    cudaGetSymbolAddress((void**)&v,    g_v);
    cudaGetSymbolAddress((void**)&ao,   g_ao);
    cudaGetSymbolAddress((void**)&attn, g_attn);

    const size_t sX = (size_t)C_DIM * AREA;
    const size_t sA = (size_t)AREA * AREA;

    // GroupNorm -> xn[b][a][c]
    groupnorm_t_kernel<<<BATCH * GROUPS, 256>>>(net, gns, gnb, xn);

    dim3 blk(256);
    dim3 gAN(C_DIM / 128, AREA / 128, BATCH);   // M=4096(a), N=512(o): (4, 32, 4)
    dim3 gNA(AREA / 128, C_DIM / 128, BATCH);   // M=512(o),  N=4096(a): (32, 4, 4)
    dim3 gAA(AREA / 128, AREA / 128, BATCH);    // (32, 32, 4)

    // Q/K: q[a][o] = sum_c xn[a][c]*wq[o][c] + bq[o]   (biasN)
    gemm_kc<<<gAN, blk>>>(xn, wq, q, AREA, C_DIM, C_DIM, sX, 0, sX, 1.f,
                          nullptr, bq, nullptr, 0);
    gemm_kc<<<gAN, blk>>>(xn, wk, k, AREA, C_DIM, C_DIM, sX, 0, sX, 1.f,
                          nullptr, bk, nullptr, 0);
    // V: v[o][a] = sum_c wv[o][c]*xn[a][c] + bv[o]     (biasM)
    gemm_kc<<<gNA, blk>>>(wv, xn, v, C_DIM, AREA, C_DIM, 0, sX, sX, 1.f,
                          bv, nullptr, nullptr, 0);

    // attn[i][j] = scale * sum_c q[i][c]*k[j][c]
    const float scale = 0.044194173824159216f;    // 512^-0.5
    gemm_kc<<<gAA, blk>>>(q, k, attn, AREA, AREA, C_DIM, sX, sX, sA, scale,
                          nullptr, nullptr, nullptr, 0);

    softmax4096<<<BATCH * AREA, 256>>>(attn);

    // ao[i][c] = sum_j attn[i][j] * v[c][j]
    gemm_kc<<<gAN, blk>>>(attn, v, ao, AREA, C_DIM, AREA, sA, sX, sX, 1.f,
                          nullptr, nullptr, nullptr, 0);

    // out[o][a] = sum_c wo[o][c]*ao[a][c] + bo[o] + net[o][a]
    gemm_kc<<<gNA, blk>>>(wo, ao, out, C_DIM, AREA, C_DIM, 0, sX, sX, 1.f,
                          bo, nullptr, net, sX);
}

// round 12
// speedup vs baseline: 1.4708x; 1.4708x over previous
#include <cuda_runtime.h>
#include <math.h>
#include <stdint.h>

#define C_DIM 512
#define AREA  4096
#define BATCH 4
#define GROUPS 32
#define CPG   16
#define GRP_F4 16384   // (CPG*AREA)/4 float4s per group

// ---------------- scratch (static device globals; no allocation) ----------------
__device__ float g_xn  [(size_t)BATCH * C_DIM * AREA];
__device__ float g_q   [(size_t)BATCH * C_DIM * AREA];
__device__ float g_k   [(size_t)BATCH * C_DIM * AREA];
__device__ float g_v   [(size_t)BATCH * C_DIM * AREA];
__device__ float g_ao  [(size_t)BATCH * C_DIM * AREA];
__device__ float g_attn[(size_t)BATCH * AREA * AREA];

// ---------------- GroupNorm (round-6 version: xn stays [c][a]) ----------------
__global__ void groupnorm_kernel(const float* __restrict__ net,
                                 const float* __restrict__ gscale,
                                 const float* __restrict__ gbias,
                                 float* __restrict__ xn) {
    const int bg = blockIdx.x;          // 0..127
    const int b  = bg >> 5;
    const int g  = bg & 31;
    const size_t base = ((size_t)b * C_DIM + (size_t)g * CPG) * AREA;
    const float4* src4 = (const float4*)(net + base);
    float4* dst4 = (float4*)(xn + base);
    const int tid = threadIdx.x;

    float s = 0.f, ss = 0.f;
    for (int i = tid; i < GRP_F4; i += 256) {
        float4 v = src4[i];
        s  += v.x + v.y + v.z + v.w;
        ss += v.x*v.x + v.y*v.y + v.z*v.z + v.w*v.w;
    }
    __shared__ float red[512];
    red[tid] = s; red[256 + tid] = ss;
    __syncthreads();
    for (int off = 128; off > 0; off >>= 1) {
        if (tid < off) {
            red[tid]       += red[tid + off];
            red[256 + tid] += red[256 + tid + off];
        }
        __syncthreads();
    }
    const float inv_n = 1.0f / 65536.0f;
    const float mu   = red[0] * inv_n;
    const float var  = red[256] * inv_n - mu * mu;
    const float rstd = rsqrtf(var + 1e-6f);

    for (int i = tid; i < GRP_F4; i += 256) {
        const int c_local = i >> 10;
        const float sc = gscale[g * CPG + c_local] * rstd;
        const float bi = gbias[g * CPG + c_local];
        float4 v = src4[i];
        v.x = (v.x - mu) * sc + bi;
        v.y = (v.y - mu) * sc + bi;
        v.z = (v.z - mu) * sc + bi;
        v.w = (v.w - mu) * sc + bi;
        dst4[i] = v;
    }
}

// ---------------- async copy helper ----------------
__device__ __forceinline__ void cp16(uint32_t dst_smem, const void* src) {
    asm volatile("cp.async.cg.shared.global [%0], [%1], 16;\n"
                 :: "r"(dst_smem), "l"(src));
}

// ---------------- tensor-core tf32 GEMM, cp.async double-buffered ----------------
// C[m,n] = alpha * sum_k Aval(m,k)*Bval(k,n) + bias[m] + resid[m,n]
// TA=0: A row-major [M,K] (K-contiguous) ; TA=1: A stored [K,M] (M-contiguous)
// TB=0: B row-major [K,N] (N-contiguous) ; TB=1: B stored [N,K] (K-contiguous)
// Block 128x128, BK=32, 256 threads (8 warps of 64x32), mma m16n8k8 tf32.
// Raw fp32 is stored in smem; mma.tf32 truncates in hardware (no cvt ALU).
// Smem layouts (round-6, verified conflict-free for fragment gathers):
//   K-contiguous operand  -> [row][k]  stride 36  (banks 4g+tg: all distinct)
//   MN-contiguous operand -> [k][col]  stride 136 (banks 8tg+g: all distinct)
// Both 16B-aligned per float4 chunk (36*4=144, 136*4=544: multiples of 16).
template<int TA, int TB>
__global__ __launch_bounds__(256, 2)
void gemm_db(const float* __restrict__ A, const float* __restrict__ B,
             float* __restrict__ C,
             int M, int N, int K,
             size_t sAb, size_t sBb, size_t sCb,
             float alpha,
             const float* __restrict__ bias,
             const float* __restrict__ resid, size_t sRb) {
    constexpr int AW = (TA == 0) ? 128 * 36 : 32 * 136;   // words per A stage
    constexpr int BW = (TB == 0) ? 32 * 136 : 128 * 36;   // words per B stage
    extern __shared__ uint32_t sm[];                      // 2*(AW+BW) words

    const int tid  = threadIdx.x;
    const int warp = tid >> 5;
    const int lane = tid & 31;
    const int g    = lane >> 2;     // 0..7
    const int tg   = lane & 3;      // 0..3
    const int warpM = warp >> 2;    // 0..1  (64 rows)
    const int warpN = warp & 3;     // 0..3  (32 cols)
    const int n0 = blockIdx.x * 128;
    const int m0 = blockIdx.y * 128;
    const int bz = blockIdx.z;

    const float4* A4 = (const float4*)(A + (size_t)bz * sAb);
    const float4* B4 = (const float4*)(B + (size_t)bz * sBb);
    const int K4 = K >> 2, N4 = N >> 2, M4 = M >> 2;
    const uint32_t sb = (uint32_t)__cvta_generic_to_shared(sm);

    float acc[4][4][4];
    #pragma unroll
    for (int mt = 0; mt < 4; ++mt)
        #pragma unroll
        for (int nt = 0; nt < 4; ++nt)
            #pragma unroll
            for (int r = 0; r < 4; ++r) acc[mt][nt][r] = 0.f;

    // ---- async fill of one stage ----
    auto fill = [&](int stage, int k0) {
        const uint32_t aBase = sb + (uint32_t)(stage * AW) * 4u;
        const uint32_t bBase = sb + (uint32_t)(2 * AW + stage * BW) * 4u;
        #pragma unroll
        for (int j = 0; j < 4; ++j) {
            const int l4 = j * 256 + tid;
            if (TA == 0) {
                const int kk4 = l4 & 7, mm = l4 >> 3;
                cp16(aBase + (uint32_t)(mm * 36 + kk4 * 4) * 4u,
                     &A4[(size_t)(m0 + mm) * K4 + (k0 >> 2) + kk4]);
            } else {
                const int mm4 = l4 & 31, kk = l4 >> 5;
                cp16(aBase + (uint32_t)(kk * 136 + mm4 * 4) * 4u,
                     &A4[(size_t)(k0 + kk) * M4 + (m0 >> 2) + mm4]);
            }
        }
        #pragma unroll
        for (int j = 0; j < 4; ++j) {
            const int l4 = j * 256 + tid;
            if (TB == 0) {
                const int nn4 = l4 & 31, kk = l4 >> 5;
                cp16(bBase + (uint32_t)(kk * 136 + nn4 * 4) * 4u,
                     &B4[(size_t)(k0 + kk) * N4 + (n0 >> 2) + nn4]);
            } else {
                const int kk4 = l4 & 7, nn = l4 >> 3;
                cp16(bBase + (uint32_t)(nn * 36 + kk4 * 4) * 4u,
                     &B4[(size_t)(n0 + nn) * K4 + (k0 >> 2) + kk4]);
            }
        }
        asm volatile("cp.async.commit_group;\n" ::: "memory");
    };

    fill(0, 0);
    const int T = K >> 5;
    for (int t = 0; t < T; ++t) {
        if (t + 1 < T) {
            fill((t + 1) & 1, (t + 1) * 32);
            asm volatile("cp.async.wait_group 1;\n" ::: "memory");
        } else {
            asm volatile("cp.async.wait_group 0;\n" ::: "memory");
        }
        __syncthreads();

        const uint32_t* As = sm + (t & 1) * AW;
        const uint32_t* Bs = sm + 2 * AW + (t & 1) * BW;

        #pragma unroll
        for (int ks = 0; ks < 4; ++ks) {
            const int kb = ks * 8;
            uint32_t af[4][4], bf[4][2];
            #pragma unroll
            for (int mt = 0; mt < 4; ++mt) {
                const int mb = warpM * 64 + mt * 16;
                if (TA == 0) {
                    af[mt][0] = As[(mb + g) * 36     + kb + tg];
                    af[mt][1] = As[(mb + g + 8) * 36 + kb + tg];
                    af[mt][2] = As[(mb + g) * 36     + kb + tg + 4];
                    af[mt][3] = As[(mb + g + 8) * 36 + kb + tg + 4];
                } else {
                    af[mt][0] = As[(kb + tg) * 136     + mb + g];
                    af[mt][1] = As[(kb + tg) * 136     + mb + g + 8];
                    af[mt][2] = As[(kb + tg + 4) * 136 + mb + g];
                    af[mt][3] = As[(kb + tg + 4) * 136 + mb + g + 8];
                }
            }
            #pragma unroll
            for (int nt = 0; nt < 4; ++nt) {
                const int nb = warpN * 32 + nt * 8;
                if (TB == 0) {
                    bf[nt][0] = Bs[(kb + tg) * 136     + nb + g];
                    bf[nt][1] = Bs[(kb + tg + 4) * 136 + nb + g];
                } else {
                    bf[nt][0] = Bs[(nb + g) * 36 + kb + tg];
                    bf[nt][1] = Bs[(nb + g) * 36 + kb + tg + 4];
                }
            }
            #pragma unroll
            for (int mt = 0; mt < 4; ++mt)
                #pragma unroll
                for (int nt = 0; nt < 4; ++nt) {
                    float* c = acc[mt][nt];
                    asm volatile(
                        "mma.sync.aligned.m16n8k8.row.col.f32.tf32.tf32.f32 "
                        "{%0,%1,%2,%3}, {%4,%5,%6,%7}, {%8,%9}, {%0,%1,%2,%3};\n"
                        : "+f"(c[0]), "+f"(c[1]), "+f"(c[2]), "+f"(c[3])
                        : "r"(af[mt][0]), "r"(af[mt][1]), "r"(af[mt][2]), "r"(af[mt][3]),
                          "r"(bf[nt][0]), "r"(bf[nt][1]));
                }
        }
        __syncthreads();
    }

    // ---- epilogue ----
    float* Cb = C + (size_t)bz * sCb;
    const float* Rb = resid ? (resid + (size_t)bz * sRb) : nullptr;

    #pragma unroll
    for (int mt = 0; mt < 4; ++mt) {
        const int mb = m0 + warpM * 64 + mt * 16;
        const int r0 = mb + g, r1 = mb + g + 8;
        const float bi0 = bias ? bias[r0] : 0.f;
        const float bi1 = bias ? bias[r1] : 0.f;
        #pragma unroll
        for (int nt = 0; nt < 4; ++nt) {
            const int nn = n0 + warpN * 32 + nt * 8 + 2 * tg;
            const size_t o0 = (size_t)r0 * N + nn;
            const size_t o1 = (size_t)r1 * N + nn;
            float2 v0 = { alpha * acc[mt][nt][0] + bi0, alpha * acc[mt][nt][1] + bi0 };
            float2 v1 = { alpha * acc[mt][nt][2] + bi1, alpha * acc[mt][nt][3] + bi1 };
            if (Rb) {
                v0.x += Rb[o0]; v0.y += Rb[o0 + 1];
                v1.x += Rb[o1]; v1.y += Rb[o1 + 1];
            }
            *(float2*)&Cb[o0] = v0;
            *(float2*)&Cb[o1] = v1;
        }
    }
}

// ---------------- softmax over rows of length 4096 ----------------
__global__ void softmax4096(float* __restrict__ attn) {
    const size_t row = blockIdx.x;
    float* p = attn + row * AREA;
    const int tid = threadIdx.x;

    float4 r[4];
    #pragma unroll
    for (int i = 0; i < 4; ++i)
        r[i] = *(const float4*)&p[(tid + i * 256) * 4];

    float m = -3.0e38f;
    #pragma unroll
    for (int i = 0; i < 4; ++i)
        m = fmaxf(m, fmaxf(fmaxf(r[i].x, r[i].y), fmaxf(r[i].z, r[i].w)));
    __shared__ float red[256];
    red[tid] = m; __syncthreads();
    for (int off = 128; off > 0; off >>= 1) {
        if (tid < off) red[tid] = fmaxf(red[tid], red[tid + off]);
        __syncthreads();
    }
    m = red[0];
    __syncthreads();

    float s = 0.f;
    #pragma unroll
    for (int i = 0; i < 4; ++i) {
        r[i].x = __expf(r[i].x - m); r[i].y = __expf(r[i].y - m);
        r[i].z = __expf(r[i].z - m); r[i].w = __expf(r[i].w - m);
        s += r[i].x + r[i].y + r[i].z + r[i].w;
    }
    red[tid] = s; __syncthreads();
    for (int off = 128; off > 0; off >>= 1) {
        if (tid < off) red[tid] += red[tid + off];
        __syncthreads();
    }
    const float inv = 1.0f / red[0];

    #pragma unroll
    for (int i = 0; i < 4; ++i) {
        r[i].x *= inv; r[i].y *= inv; r[i].z *= inv; r[i].w *= inv;
        *(float4*)&p[(tid + i * 256) * 4] = r[i];
    }
}

// ---------------- launch ----------------
extern "C" void kernel_launch(void* const* d_in, const int* in_sizes, int n_in,
                              void* d_out, int out_size) {
    const float* net = (const float*)d_in[0];
    const float* gns = (const float*)d_in[1];
    const float* gnb = (const float*)d_in[2];
    const float* wq  = (const float*)d_in[3];
    const float* bq  = (const float*)d_in[4];
    const float* wk  = (const float*)d_in[5];
    const float* bk  = (const float*)d_in[6];
    const float* wv  = (const float*)d_in[7];
    const float* bv  = (const float*)d_in[8];
    const float* wo  = (const float*)d_in[9];
    const float* bo  = (const float*)d_in[10];
    float* out = (float*)d_out;

    float *xn, *q, *k, *v, *ao, *attn;
    cudaGetSymbolAddress((void**)&xn,   g_xn);
    cudaGetSymbolAddress((void**)&q,    g_q);
    cudaGetSymbolAddress((void**)&k,    g_k);
    cudaGetSymbolAddress((void**)&v,    g_v);
    cudaGetSymbolAddress((void**)&ao,   g_ao);
    cudaGetSymbolAddress((void**)&attn, g_attn);

    const size_t sX = (size_t)C_DIM * AREA;
    const size_t sA = (size_t)AREA * AREA;

    // dynamic smem sizes per instantiation: 2*(AW+BW)*4 bytes
    const int SM00 = 2 * (128 * 36 + 32 * 136) * 4;   // 71680
    const int SM10 = 2 * (32 * 136 + 32 * 136) * 4;   // 69632
    const int SM01 = 2 * (128 * 36 + 128 * 36) * 4;   // 73728
    cudaFuncSetAttribute(gemm_db<0, 0>, cudaFuncAttributeMaxDynamicSharedMemorySize, SM00);
    cudaFuncSetAttribute(gemm_db<1, 0>, cudaFuncAttributeMaxDynamicSharedMemorySize, SM10);
    cudaFuncSetAttribute(gemm_db<0, 1>, cudaFuncAttributeMaxDynamicSharedMemorySize, SM01);

    groupnorm_kernel<<<BATCH * GROUPS, 256>>>(net, gns, gnb, xn);

    dim3 blk(256);
    dim3 gProj(AREA / 128, C_DIM / 128, BATCH);   // (32, 4, 4)
    // Q/K/V: W[o,c] @ xn[c,a] + b
    gemm_db<0, 0><<<gProj, blk, SM00>>>(wq, xn, q, C_DIM, AREA, C_DIM, 0, sX, sX, 1.f, bq, nullptr, 0);
    gemm_db<0, 0><<<gProj, blk, SM00>>>(wk, xn, k, C_DIM, AREA, C_DIM, 0, sX, sX, 1.f, bk, nullptr, 0);
    gemm_db<0, 0><<<gProj, blk, SM00>>>(wv, xn, v, C_DIM, AREA, C_DIM, 0, sX, sX, 1.f, bv, nullptr, 0);

    // attn[i,j] = scale * sum_c q[c,i] * k[c,j]   (TN: A stored [K,M])
    dim3 gAttn(AREA / 128, AREA / 128, BATCH);    // (32, 32, 4)
    const float scale = 0.044194173824159216f;    // 512^-0.5
    gemm_db<1, 0><<<gAttn, blk, SM10>>>(q, k, attn, AREA, AREA, C_DIM, sX, sX, sA, scale,
                                        nullptr, nullptr, 0);

    softmax4096<<<BATCH * AREA, 256>>>(attn);

    // ao[c,i] = sum_j v[c,j] * p[i,j]   (NT: B stored [N,K])
    gemm_db<0, 1><<<gProj, blk, SM01>>>(v, attn, ao, C_DIM, AREA, AREA, sX, sA, sX, 1.f,
                                        nullptr, nullptr, 0);

    // out = net + Wo @ ao + bo
    gemm_db<0, 0><<<gProj, blk, SM00>>>(wo, ao, out, C_DIM, AREA, C_DIM, 0, sX, sX, 1.f,
                                        bo, net, sX);
}